// round 3
// baseline (speedup 1.0000x reference)
#include <cuda_runtime.h>
#include <math.h>

#define B_ 2
#define C_ 256
#define N_ 4096
#define D_ 64
#define K_ 32
#define M_ 256
#define R_ 416
#define INVSCALE (1.0f/8.000001f)

// ----------------------------- scratch -----------------------------
__device__ float g_W[R_*C_];
__device__ float g_bias[R_];
__device__ float g_P[B_*R_*N_];        // [sem(32); q(64); k(64); fv(256)] x N
__device__ float g_sem[B_*K_*N_];
__device__ int   g_ti[B_*K_*M_];
__device__ int   g_cnt[B_*K_];
__device__ int   g_plist[B_*K_*N_];
__device__ float g_qT[B_*N_*D_];
__device__ float g_kT[B_*N_*D_];
__device__ float g_fvT[B_*N_*C_];
__device__ float g_xT[B_*N_*C_];
__device__ float g_part[8*B_*K_*320];
__device__ float g_RK[B_*K_*D_];
__device__ float g_RFV[B_*K_*C_];
__device__ float g_outT[B_*N_*C_];

// ----------------------------- kernels -----------------------------
__global__ void k_zero() {
    if (threadIdx.x < B_*K_) g_cnt[threadIdx.x] = 0;
}

// Build Wcat = [sem_w; q_w; k_w; fuse_w@v_w] and bias
__global__ void k_prep(const float* __restrict__ sem_w, const float* __restrict__ sem_b,
                       const float* __restrict__ q_w,  const float* __restrict__ k_w,
                       const float* __restrict__ v_w,  const float* __restrict__ fuse_w) {
    __shared__ float fw[C_];
    int r = blockIdx.x, c = threadIdx.x;
    if (r >= 160) fw[c] = fuse_w[(r-160)*C_ + c];
    __syncthreads();
    float val;
    if (r < 32)       val = sem_w[r*C_ + c];
    else if (r < 96)  val = q_w[(r-32)*C_ + c];
    else if (r < 160) val = k_w[(r-96)*C_ + c];
    else {
        float acc = 0.f;
        #pragma unroll 8
        for (int m = 0; m < C_; m++) acc += fw[m] * v_w[m*C_ + c];
        val = acc;
    }
    g_W[r*C_ + c] = val;
    if (c == 0) g_bias[r] = (r < 32) ? sem_b[r] : 0.f;
}

// P[b,r,n] = Wcat[r,:] @ x[b,:,n] + bias[r]   (64x64 tile, 256 thr, 4x4 micro)
__global__ void __launch_bounds__(256) k_gemm(const float* __restrict__ x) {
    __shared__ float As[16][68];
    __shared__ float Bs[16][68];
    int n0 = blockIdx.x*64, r0 = blockIdx.y*64, b = blockIdx.z;
    int tid = threadIdx.x;
    int tx = tid & 15, ty = tid >> 4;
    float acc[4][4] = {};
    const float* xb = x + b*C_*N_;
    for (int kc = 0; kc < C_; kc += 16) {
        #pragma unroll
        for (int i = 0; i < 4; i++) {
            int e = tid + i*256;
            int rr = e >> 4, kk = e & 15;
            int r = r0 + rr;
            As[kk][rr] = (r < R_) ? g_W[r*C_ + kc + kk] : 0.f;
        }
        #pragma unroll
        for (int i = 0; i < 4; i++) {
            int e = tid + i*256;
            int kk = e >> 6, nn = e & 63;
            Bs[kk][nn] = xb[(kc+kk)*N_ + n0 + nn];
        }
        __syncthreads();
        #pragma unroll
        for (int kk = 0; kk < 16; kk++) {
            float4 av = *(const float4*)&As[kk][ty*4];
            float4 bv = *(const float4*)&Bs[kk][tx*4];
            float aa[4] = {av.x, av.y, av.z, av.w};
            float bb[4] = {bv.x, bv.y, bv.z, bv.w};
            #pragma unroll
            for (int i = 0; i < 4; i++)
                #pragma unroll
                for (int j = 0; j < 4; j++) acc[i][j] += aa[i]*bb[j];
        }
        __syncthreads();
    }
    #pragma unroll
    for (int i = 0; i < 4; i++) {
        int r = r0 + ty*4 + i;
        if (r < R_) {
            float bi = g_bias[r];
            float4 o = make_float4(acc[i][0]+bi, acc[i][1]+bi, acc[i][2]+bi, acc[i][3]+bi);
            *(float4*)&g_P[(b*R_ + r)*N_ + n0 + tx*4] = o;
        }
    }
}

// softmax over K per position + argmax bucketing
__global__ void k_sem() {
    int gid = blockIdx.x*256 + threadIdx.x;       // 8192 total
    int b = gid >> 12, n = gid & (N_-1);
    float l[K_];
    float mx = -INFINITY; int am = 0;
    #pragma unroll
    for (int k = 0; k < K_; k++) {
        l[k] = g_P[(b*R_ + k)*N_ + n];
        if (l[k] > mx) { mx = l[k]; am = k; }
    }
    float s = 0.f;
    #pragma unroll
    for (int k = 0; k < K_; k++) { l[k] = expf(l[k]-mx); s += l[k]; }
    float inv = 1.f/s;
    #pragma unroll
    for (int k = 0; k < K_; k++) g_sem[(b*K_ + k)*N_ + n] = l[k]*inv;
    int slot = atomicAdd(&g_cnt[b*K_ + am], 1);
    g_plist[(b*K_+am)*N_ + slot] = n;
}

// exact top-256 per (b,k): bitonic sort of 4096 packed keys
__global__ void __launch_bounds__(1024) k_sort() {
    __shared__ unsigned long long s[N_];
    int bk = blockIdx.x; int b = bk >> 5, k = bk & 31;
    int tid = threadIdx.x;
    for (int i = tid; i < N_; i += 1024) {
        float v = g_sem[(b*K_+k)*N_ + i];
        unsigned long long key = ((unsigned long long)__float_as_uint(v) << 32)
                               | (unsigned)(0xFFFFFFFFu - (unsigned)i);
        s[i] = ~key;   // ascending sort of ~key == descending of key
    }
    __syncthreads();
    for (int sz = 2; sz <= N_; sz <<= 1) {
        for (int str = sz >> 1; str > 0; str >>= 1) {
            for (int i = tid; i < N_; i += 1024) {
                int l = i ^ str;
                if (l > i) {
                    unsigned long long a = s[i], c = s[l];
                    bool up = ((i & sz) == 0);
                    if ((a > c) == up) { s[i] = c; s[l] = a; }
                }
            }
            __syncthreads();
        }
    }
    if (tid < M_) {
        unsigned long long key = ~s[tid];
        g_ti[(b*K_+k)*M_ + tid] = (int)(0xFFFFFFFFu - (unsigned)(key & 0xFFFFFFFFu));
    }
}

// generic tiled transposes (mode selects src/dst)
__global__ void k_transp(int mode, const float* __restrict__ xin, float* __restrict__ dout) {
    const float* src; float* dst; int Rr, Nn, rowOff, sBS;
    if      (mode == 0) { src = g_P;    dst = g_qT;  Rr = 64;  Nn = N_;  rowOff = 32;  sBS = R_*N_; }
    else if (mode == 1) { src = g_P;    dst = g_kT;  Rr = 64;  Nn = N_;  rowOff = 96;  sBS = R_*N_; }
    else if (mode == 2) { src = g_P;    dst = g_fvT; Rr = 256; Nn = N_;  rowOff = 160; sBS = R_*N_; }
    else if (mode == 3) { src = xin;    dst = g_xT;  Rr = 256; Nn = N_;  rowOff = 0;   sBS = C_*N_; }
    else                { src = g_outT; dst = dout;  Rr = N_;  Nn = 256; rowOff = 0;   sBS = N_*C_; }
    __shared__ float t[32][33];
    int b = blockIdx.z;
    int x0 = blockIdx.x*32, r0 = blockIdx.y*32;
    int tx = threadIdx.x, ty = threadIdx.y;
    #pragma unroll
    for (int i = 0; i < 32; i += 8)
        t[ty+i][tx] = src[b*sBS + (rowOff + r0 + ty + i)*Nn + x0 + tx];
    __syncthreads();
    #pragma unroll
    for (int i = 0; i < 32; i += 8)
        dst[b*Nn*Rr + (x0 + ty + i)*Rr + r0 + tx] = t[tx][ty+i];
}

// region_k / region_fv = sem @ [k; fv]^T, split over N into 8 partials
__global__ void __launch_bounds__(256) k_region() {
    __shared__ float ss[32*65];
    __shared__ float ps[64*65];
    int ct = blockIdx.x, sp = blockIdx.y, b = blockIdx.z;
    int tid = threadIdx.x;
    int kk = tid & 31, cg = tid >> 5;   // c0 = cg*8
    float acc[8] = {};
    for (int nch = 0; nch < 8; nch++) {
        int nn0 = sp*512 + nch*64;
        #pragma unroll
        for (int i = 0; i < 8; i++) {
            int e = tid + i*256; int kr = e >> 6, nn = e & 63;
            ss[kr*65+nn] = g_sem[(b*K_+kr)*N_ + nn0 + nn];
        }
        #pragma unroll
        for (int i = 0; i < 16; i++) {
            int e = tid + i*256; int c = e >> 6, nn = e & 63;
            ps[c*65+nn] = g_P[(b*R_ + 96 + ct*64 + c)*N_ + nn0 + nn];
        }
        __syncthreads();
        for (int nn = 0; nn < 64; nn++) {
            float sv = ss[kk*65+nn];
            #pragma unroll
            for (int j = 0; j < 8; j++) acc[j] += sv * ps[(cg*8+j)*65+nn];
        }
        __syncthreads();
    }
    #pragma unroll
    for (int j = 0; j < 8; j++) {
        int o = ct*64 + cg*8 + j;
        g_part[((sp*B_+b)*K_+kk)*320 + o] = acc[j];
    }
}

__global__ void k_reduce() {
    int og = blockIdx.x*256 + threadIdx.x;           // 20480 total
    int b = og / (K_*320); int rem = og % (K_*320);
    int kk = rem / 320, o = rem % 320;
    float s = 0.f;
    #pragma unroll
    for (int sp = 0; sp < 8; sp++) s += g_part[((sp*B_+b)*K_+kk)*320 + o];
    if (o < 64) g_RK[(b*K_+kk)*D_ + o] = s;
    else        g_RFV[(b*K_+kk)*C_ + (o-64)] = s;
}

// fused main: sims -> top8 -> sparse, dense attn, combine, residual, channel-LN
__global__ void __launch_bounds__(256) k_main(const float* __restrict__ alpha_p,
                                              const float* __restrict__ fuse_b,
                                              const float* __restrict__ ln_g,
                                              const float* __restrict__ ln_b) {
    extern __shared__ float sm[];
    float* s_pkT = sm;                         // 64*257
    float* s_rfv = s_pkT + 64*257;             // 32*256
    float* s_rk  = s_rfv + 32*256;             // 32*65
    float* s_q   = s_rk  + 32*65;              // 8*64
    int*   s_pool= (int*)(s_q + 8*64);         // 256

    int chunk = blockIdx.x, reg = blockIdx.y, b = blockIdx.z;
    int cnt = g_cnt[b*K_ + reg];
    int base = chunk*64;
    if (base >= cnt) return;
    int tid = threadIdx.x, lane = tid & 31, w = tid >> 5;

    if (tid < M_) s_pool[tid] = g_ti[(b*K_+reg)*M_ + tid];
    __syncthreads();
    #pragma unroll 4
    for (int i = 0; i < 64; i++) {
        int e = tid + i*256;
        int m = e >> 6, d = e & 63;
        s_pkT[d*257 + m] = g_kT[(b*N_ + s_pool[m])*D_ + d];
    }
    #pragma unroll
    for (int i = 0; i < 32; i++) s_rfv[tid + i*256] = g_RFV[b*K_*C_ + tid + i*256];
    #pragma unroll
    for (int i = 0; i < 8; i++) {
        int e = tid + i*256; int kk = e >> 6, d = e & 63;
        s_rk[kk*65+d] = g_RK[(b*K_+kk)*D_ + d];
    }
    __syncthreads();

    float a = 1.f/(1.f + expf(-alpha_p[0]));
    int pend = min(base+64, cnt);

    for (int p = base + w; p < pend; p += 8) {
        int n = g_plist[(b*K_+reg)*N_ + p];
        float* qw = s_q + w*64;
        qw[lane]    = g_qT[(b*N_+n)*D_ + lane];
        qw[32+lane] = g_qT[(b*N_+n)*D_ + 32 + lane];
        __syncwarp();

        // sims over the 256-entry pool: lane owns m = mi*32+lane
        float sims[8] = {};
        for (int d = 0; d < 64; d++) {
            float qd = qw[d];
            const float* row = s_pkT + d*257;
            #pragma unroll
            for (int mi = 0; mi < 8; mi++) sims[mi] += qd * row[mi*32 + lane];
        }
        #pragma unroll
        for (int mi = 0; mi < 8; mi++) sims[mi] *= INVSCALE;

        // exact warp top-8 (value desc, pool index asc on ties)
        float tv[8]; int tm[8];
        unsigned used = 0;
        #pragma unroll
        for (int t = 0; t < 8; t++) {
            float bv = -INFINITY; int bm = 1 << 30;
            #pragma unroll
            for (int mi = 0; mi < 8; mi++) {
                if (!(used & (1u << mi))) {
                    float v = sims[mi]; int m = mi*32 + lane;
                    if (v > bv || (v == bv && m < bm)) { bv = v; bm = m; }
                }
            }
            #pragma unroll
            for (int off = 16; off > 0; off >>= 1) {
                float ov = __shfl_xor_sync(0xFFFFFFFFu, bv, off);
                int   om = __shfl_xor_sync(0xFFFFFFFFu, bm, off);
                if (ov > bv || (ov == bv && om < bm)) { bv = ov; bm = om; }
            }
            tv[t] = bv; tm[t] = bm;
            if ((bm & 31) == lane) used |= 1u << (bm >> 5);
        }
        // softmax over tv (tv[0] is the max)
        float ww[8], wsum = 0.f;
        #pragma unroll
        for (int t = 0; t < 8; t++) { ww[t] = expf(tv[t] - tv[0]); wsum += ww[t]; }
        float winv = 1.f/wsum;
        // sparse branch (fused): gather fv rows
        float fs[8] = {};
        #pragma unroll
        for (int t = 0; t < 8; t++) {
            float att = ww[t]*winv;
            int gidx = s_pool[tm[t]];
            const float* fvrow = g_fvT + (b*N_ + gidx)*C_;
            #pragma unroll
            for (int j = 0; j < 8; j++) fs[j] += att * fvrow[j*32 + lane];
        }
        // dense branch: logit for region k = lane
        float lg = 0.f;
        for (int d = 0; d < 64; d++) lg += qw[d]*s_rk[lane*65 + d];
        lg *= INVSCALE;
        float mx = lg;
        #pragma unroll
        for (int off = 16; off > 0; off >>= 1)
            mx = fmaxf(mx, __shfl_xor_sync(0xFFFFFFFFu, mx, off));
        float ev = expf(lg - mx), es = ev;
        #pragma unroll
        for (int off = 16; off > 0; off >>= 1) es += __shfl_xor_sync(0xFFFFFFFFu, es, off);
        float attn = ev/es;
        float fc[8] = {};
        for (int kk = 0; kk < K_; kk++) {
            float ak = __shfl_sync(0xFFFFFFFFu, attn, kk);
            const float* rrow = s_rfv + kk*256;
            #pragma unroll
            for (int j = 0; j < 8; j++) fc[j] += ak * rrow[j*32 + lane];
        }
        // combine + fuse bias + residual + channel LayerNorm
        float pre[8], sum = 0.f, sq = 0.f;
        const float* xrow = g_xT + (b*N_+n)*C_;
        #pragma unroll
        for (int j = 0; j < 8; j++) {
            int c = j*32 + lane;
            float f = a*fc[j] + (1.f - a)*fs[j] + fuse_b[c];
            float v = xrow[c] + f;
            pre[j] = v; sum += v; sq += v*v;
        }
        #pragma unroll
        for (int off = 16; off > 0; off >>= 1) {
            sum += __shfl_xor_sync(0xFFFFFFFFu, sum, off);
            sq  += __shfl_xor_sync(0xFFFFFFFFu, sq,  off);
        }
        float mu = sum * (1.f/256.f);
        float var = sq * (1.f/256.f) - mu*mu;
        float rstd = rsqrtf(var + 1e-5f);
        float* orow = g_outT + (b*N_+n)*C_;
        #pragma unroll
        for (int j = 0; j < 8; j++) {
            int c = j*32 + lane;
            orow[c] = (pre[j]-mu)*rstd*ln_g[c] + ln_b[c];
        }
    }
}

// ----------------------------- launch -----------------------------
extern "C" void kernel_launch(void* const* d_in, const int* in_sizes, int n_in,
                              void* d_out, int out_size) {
    const float* x      = (const float*)d_in[0];
    const float* sem_w  = (const float*)d_in[1];
    const float* sem_b  = (const float*)d_in[2];
    const float* q_w    = (const float*)d_in[3];
    const float* k_w    = (const float*)d_in[4];
    const float* v_w    = (const float*)d_in[5];
    const float* fuse_w = (const float*)d_in[6];
    const float* fuse_b = (const float*)d_in[7];
    const float* alpha  = (const float*)d_in[8];
    const float* ln_g   = (const float*)d_in[9];
    const float* ln_b   = (const float*)d_in[10];
    float* out = (float*)d_out;

    const int SMEM_MAIN = (64*257 + 32*256 + 32*65 + 8*64)*4 + 256*4;
    cudaFuncSetAttribute((const void*)k_main,
                         cudaFuncAttributeMaxDynamicSharedMemorySize, SMEM_MAIN);

    k_zero<<<1, 64>>>();
    k_prep<<<R_, 256>>>(sem_w, sem_b, q_w, k_w, v_w, fuse_w);
    k_gemm<<<dim3(64, 7, B_), 256>>>(x);
    k_sem<<<32, 256>>>();
    k_sort<<<B_*K_, 1024>>>();
    k_transp<<<dim3(128, 2, B_), dim3(32, 8)>>>(0, x, out);  // qT
    k_transp<<<dim3(128, 2, B_), dim3(32, 8)>>>(1, x, out);  // kT
    k_transp<<<dim3(128, 8, B_), dim3(32, 8)>>>(2, x, out);  // fvT
    k_transp<<<dim3(128, 8, B_), dim3(32, 8)>>>(3, x, out);  // xT
    k_region<<<dim3(5, 8, B_), 256>>>();
    k_reduce<<<80, 256>>>();
    k_main<<<dim3(64, K_, B_), 256, SMEM_MAIN>>>(alpha, fuse_b, ln_g, ln_b);
    k_transp<<<dim3(8, 128, B_), dim3(32, 8)>>>(4, x, out);  // outT -> (B,C,N)
}